// round 8
// baseline (speedup 1.0000x reference)
#include <cuda_runtime.h>

// ---------------- Problem constants (fixed-shape problem) ----------------
#define N_IN    200000
#define N_OUT   100000
#define KK      9
#define C_IN    32
#define C_A     24
#define C_B     8
#define E_MAX   1600000
#define T_TOT   (KK * C_IN)     // 288 reduction terms
#define P_TOT   (T_TOT / 2)     // 144 f32x2 pairs

// ---------------- Tiling ----------------
#define G              8                    // outputs per warp
#define WARPS_PER_BLK  2
#define OUT_PER_BLK    (G * WARPS_PER_BLK)  // 16
#define SB_OFF         292                  // Sb offset within a slot (16B bank shift)
#define PER_OUT        580                  // 288 Sa + 4 pad + 288 Sb
#define SMEM_FLOATS    (WARPS_PER_BLK * G * PER_OUT)   // 9280 floats = 37120 B static

// Packed f32x2 FMA (FFMA2): 2 fp32 MACs / instruction, PTX-only on sm_103a.
#define FFMA2(acc, a, b) \
    asm("fma.rn.f32x2 %0, %1, %2, %0;" : "+l"(acc) : "l"(a), "l"(b))

// ---------------- Device scratch (no cudaMalloc allowed) ----------------
__device__ int                g_row_start[N_OUT + 1];
__device__ unsigned long long g_Wp[P_TOT * 32];  // pair-major merged weights:
                                                 // [p][f] = (W[2p][f], W[2p+1][f]);
                                                 // f<24 -> W_a, else W_b col f-24
__device__ unsigned           g_packed[E_MAX];   // (kbin << 24) | input_index
__device__ float              g_impe[E_MAX];     // importance[input_index] per edge

// ---------------------------------------------------------------------------
// Fused prepass (one launch):
//   t < e_count      : pack (k,idx), pre-gather per-edge importance
//   t <= N_OUT       : CSR row offset via binary search on sorted out_idx
//   t < P_TOT*32     : pair-major merged weight table
// ---------------------------------------------------------------------------
__global__ void prepass_kernel(const int* __restrict__ nidx,
                               const int* __restrict__ nk,
                               const float* __restrict__ importance,
                               const int* __restrict__ out_idx,
                               const float* __restrict__ Wa,
                               const float* __restrict__ Wb,
                               int e_count) {
    const int t = blockIdx.x * blockDim.x + threadIdx.x;

    if (t < e_count) {
        const int idx = __ldg(nidx + t);
        g_packed[t] = (unsigned)idx | ((unsigned)__ldg(nk + t) << 24);
        g_impe[t]   = __ldg(importance + idx);
    }

    if (t <= N_OUT) {
        int lo = 0, hi = e_count;
        while (lo < hi) {
            int mid = (lo + hi) >> 1;
            if (__ldg(out_idx + mid) < t) lo = mid + 1; else hi = mid;
        }
        g_row_start[t] = lo;
    }

    if (t < P_TOT * 32) {
        const int f = t & 31;
        const int p = t >> 5;
        const int t0 = 2 * p, t1 = 2 * p + 1;
        const float lo = (f < C_A) ? __ldg(Wa + t0 * C_A + f) : __ldg(Wb + t0 * C_B + (f - C_A));
        const float hi = (f < C_A) ? __ldg(Wa + t1 * C_A + f) : __ldg(Wb + t1 * C_B + (f - C_A));
        unsigned long long v;
        asm("mov.b64 %0, {%1, %2};" : "=l"(v) : "f"(lo), "f"(hi));
        g_Wp[t] = v;
    }
}

// ---------------------------------------------------------------------------
// Main fused kernel: one warp owns G=8 output points.
// Phase 1: accumulate Sa[k][c], Sb[k][c], imp_sum (warp-private, no atomics)
// Phase 2: einsum over 288 terms via packed FFMA2: s-pairs come free from
//          LDS.128 (contiguous t), w-pairs from the pair-major LDG.64 table,
//          reused across all G outputs.
// No __syncthreads anywhere: every shared word is touched by exactly one warp.
// ---------------------------------------------------------------------------
__global__ __launch_bounds__(WARPS_PER_BLK * 32)
void sparse_conv_kernel(const float* __restrict__ feats,
                        const float* __restrict__ ba,
                        const float* __restrict__ bb,
                        float* __restrict__ out) {
    __shared__ __align__(16) float sm[SMEM_FLOATS];

    const int lane = threadIdx.x & 31;
    const int warp = threadIdx.x >> 5;
    float* Sw = sm + warp * (G * PER_OUT);
    const int o0 = (blockIdx.x * WARPS_PER_BLK + warp) * G;

    // Coalesced prefetch of this warp's G+1 row bounds (lane i holds bound i).
    int myBound = 0;
    if (lane <= G) myBound = g_row_start[o0 + lane];

    // Zero this warp's private region.
    #pragma unroll
    for (int g = 0; g < G; ++g) {
        float* p = Sw + g * PER_OUT;
        #pragma unroll
        for (int i = 0; i < KK; ++i) {
            p[i * 32 + lane]          = 0.f;
            p[SB_OFF + i * 32 + lane] = 0.f;
        }
    }

    float imps[G];

    // ---------------- Phase 1: edge accumulation ----------------
    for (int g = 0; g < G; ++g) {
        float* sa = Sw + g * PER_OUT;
        float* sb = sa + SB_OFF;
        const int e0 = __shfl_sync(0xffffffffu, myBound, g);
        const int e1 = __shfl_sync(0xffffffffu, myBound, g + 1);

        float ip = 0.f;
        #pragma unroll 1
        for (int base = e0; base < e1; base += 32) {
            const int n = min(32, e1 - base);
            unsigned pk = 0u;
            float    im = 0.f;
            if (lane < n) {
                pk = g_packed[base + lane];
                im = g_impe[base + lane];
            }
            ip += im;

            int j = 0;
            // 4 independent feats-row gathers in flight per step
            #pragma unroll 1
            for (; j + 4 <= n; j += 4) {
                const unsigned p0 = __shfl_sync(0xffffffffu, pk, j);
                const unsigned p1 = __shfl_sync(0xffffffffu, pk, j + 1);
                const unsigned p2 = __shfl_sync(0xffffffffu, pk, j + 2);
                const unsigned p3 = __shfl_sync(0xffffffffu, pk, j + 3);
                const float v0 = __ldg(feats + (p0 & 0xFFFFFFu) * C_IN + lane);
                const float v1 = __ldg(feats + (p1 & 0xFFFFFFu) * C_IN + lane);
                const float v2 = __ldg(feats + (p2 & 0xFFFFFFu) * C_IN + lane);
                const float v3 = __ldg(feats + (p3 & 0xFFFFFFu) * C_IN + lane);
                const float m0 = __shfl_sync(0xffffffffu, im, j);
                const float m1 = __shfl_sync(0xffffffffu, im, j + 1);
                const float m2 = __shfl_sync(0xffffffffu, im, j + 2);
                const float m3 = __shfl_sync(0xffffffffu, im, j + 3);
                const int k0 = (int)(p0 >> 24), k1 = (int)(p1 >> 24);
                const int k2 = (int)(p2 >> 24), k3 = (int)(p3 >> 24);
                sa[k0 * 32 + lane] += v0;  sb[k0 * 32 + lane] += v0 * m0;
                sa[k1 * 32 + lane] += v1;  sb[k1 * 32 + lane] += v1 * m1;
                sa[k2 * 32 + lane] += v2;  sb[k2 * 32 + lane] += v2 * m2;
                sa[k3 * 32 + lane] += v3;  sb[k3 * 32 + lane] += v3 * m3;
            }
            #pragma unroll 1
            for (; j < n; ++j) {
                const unsigned pj = __shfl_sync(0xffffffffu, pk, j);
                const float    mj = __shfl_sync(0xffffffffu, im, j);
                const float    v  = __ldg(feats + (pj & 0xFFFFFFu) * C_IN + lane);
                const int      kj = (int)(pj >> 24);
                sa[kj * 32 + lane] += v;
                sb[kj * 32 + lane] += v * mj;
            }
        }

        #pragma unroll
        for (int s = 16; s > 0; s >>= 1)
            ip += __shfl_xor_sync(0xffffffffu, ip, s);
        imps[g] = ip;
    }

    // ---------------- Phase 2: packed-f32x2 einsum ----------------
    // lane f<24 -> branch A (Sa, W_a); lanes 24..31 -> branch B (Sb, W_b).
    const int selOff = (lane < C_A) ? 0 : SB_OFF;

    unsigned long long acc2[G];
    #pragma unroll
    for (int g = 0; g < G; ++g) acc2[g] = 0ull;  // (0.0f, 0.0f)

    #pragma unroll 1
    for (int p0 = 0; p0 < P_TOT; p0 += 4) {      // 36 iterations, 8 t-values each
        const unsigned long long w0 = g_Wp[(p0 + 0) * 32 + lane];
        const unsigned long long w1 = g_Wp[(p0 + 1) * 32 + lane];
        const unsigned long long w2 = g_Wp[(p0 + 2) * 32 + lane];
        const unsigned long long w3 = g_Wp[(p0 + 3) * 32 + lane];
        #pragma unroll
        for (int g = 0; g < G; ++g) {
            const float* sp = Sw + g * PER_OUT + selOff + 2 * p0;
            const ulonglong2 s01 = *reinterpret_cast<const ulonglong2*>(sp);
            const ulonglong2 s23 = *reinterpret_cast<const ulonglong2*>(sp + 4);
            FFMA2(acc2[g], s01.x, w0);
            FFMA2(acc2[g], s01.y, w1);
            FFMA2(acc2[g], s23.x, w2);
            FFMA2(acc2[g], s23.y, w3);
        }
    }

    const float bias = (lane < C_A) ? __ldg(ba + lane) : __ldg(bb + lane - C_A);
    #pragma unroll
    for (int g = 0; g < G; ++g) {
        float alo, ahi;
        asm("mov.b64 {%0, %1}, %2;" : "=f"(alo), "=f"(ahi) : "l"(acc2[g]));
        const float acc = alo + ahi;
        const int o = o0 + g;
        const float isum  = imps[g];
        const float denom = (isum > 0.f) ? isum : 1.f;
        float r = (lane < C_A) ? (acc + bias) : (acc / denom + bias);
        out[o * 32 + lane] = fmaxf(r, 0.f);
        if (lane == 0) out[N_OUT * 32 + o] = isum;
    }
}

// ---------------------------------------------------------------------------
extern "C" void kernel_launch(void* const* d_in, const int* in_sizes, int n_in,
                              void* d_out, int out_size) {
    const float* feats      = (const float*)d_in[0];
    const float* importance = (const float*)d_in[1];
    const float* W_a        = (const float*)d_in[2];
    const float* b_a        = (const float*)d_in[3];
    const float* W_b        = (const float*)d_in[4];
    const float* b_b        = (const float*)d_in[5];
    const int*   n_idx      = (const int*)d_in[6];
    const int*   n_kidx     = (const int*)d_in[7];
    const int*   n_oidx     = (const int*)d_in[8];
    float* out = (float*)d_out;

    const int e_count = in_sizes[6];
    const int prep_threads = (e_count > N_OUT + 1) ? e_count : (N_OUT + 1);

    prepass_kernel<<<(prep_threads + 255) / 256, 256>>>(
        n_idx, n_kidx, importance, n_oidx, W_a, W_b, e_count);
    sparse_conv_kernel<<<N_OUT / OUT_PER_BLK, WARPS_PER_BLK * 32>>>(
        feats, b_a, b_b, out);
}

// round 9
// speedup vs baseline: 1.2190x; 1.2190x over previous
#include <cuda_runtime.h>

// ---------------- Problem constants (fixed-shape problem) ----------------
#define N_IN    200000
#define N_OUT   100000
#define KK      9
#define C_IN    32
#define C_A     24
#define C_B     8
#define E_MAX   1600000
#define T_TOT   (KK * C_IN)     // 288 reduction terms
#define P_TOT   (T_TOT / 2)     // 144 f32x2 pairs

// ---------------- Tiling ----------------
#define G              4                    // outputs per warp (R9: 8->4 for 2x occupancy)
#define WARPS_PER_BLK  4
#define OUT_PER_BLK    (G * WARPS_PER_BLK)  // 16
#define SB_OFF         292                  // Sb offset within a slot (16B bank shift)
#define PER_OUT        580                  // 288 Sa + 4 pad + 288 Sb
#define SMEM_FLOATS    (WARPS_PER_BLK * G * PER_OUT)   // 9280 floats = 37120 B static

// Packed f32x2 FMA (FFMA2): 2 fp32 MACs / instruction, PTX-only on sm_103a.
#define FFMA2(acc, a, b) \
    asm("fma.rn.f32x2 %0, %1, %2, %0;" : "+l"(acc) : "l"(a), "l"(b))

// ---------------- Device scratch (no cudaMalloc allowed) ----------------
__device__ int                g_row_start[N_OUT + 1];
__device__ unsigned long long g_Wp[P_TOT * 32];  // pair-major merged weights:
                                                 // [p][f] = (W[2p][f], W[2p+1][f]);
                                                 // f<24 -> W_a, else W_b col f-24
__device__ unsigned           g_packed[E_MAX];   // (kbin << 24) | input_index
__device__ float              g_impe[E_MAX];     // importance[input_index] per edge

// ---------------------------------------------------------------------------
// Fused prepass (one launch):
//   t < e_count      : pack (k,idx), pre-gather per-edge importance
//   t <= N_OUT       : CSR row offset via binary search on sorted out_idx
//   t < P_TOT*32     : pair-major merged weight table
// ---------------------------------------------------------------------------
__global__ void prepass_kernel(const int* __restrict__ nidx,
                               const int* __restrict__ nk,
                               const float* __restrict__ importance,
                               const int* __restrict__ out_idx,
                               const float* __restrict__ Wa,
                               const float* __restrict__ Wb,
                               int e_count) {
    const int t = blockIdx.x * blockDim.x + threadIdx.x;

    if (t < e_count) {
        const int idx = __ldg(nidx + t);
        g_packed[t] = (unsigned)idx | ((unsigned)__ldg(nk + t) << 24);
        g_impe[t]   = __ldg(importance + idx);
    }

    if (t <= N_OUT) {
        int lo = 0, hi = e_count;
        while (lo < hi) {
            int mid = (lo + hi) >> 1;
            if (__ldg(out_idx + mid) < t) lo = mid + 1; else hi = mid;
        }
        g_row_start[t] = lo;
    }

    if (t < P_TOT * 32) {
        const int f = t & 31;
        const int p = t >> 5;
        const int t0 = 2 * p, t1 = 2 * p + 1;
        const float lo = (f < C_A) ? __ldg(Wa + t0 * C_A + f) : __ldg(Wb + t0 * C_B + (f - C_A));
        const float hi = (f < C_A) ? __ldg(Wa + t1 * C_A + f) : __ldg(Wb + t1 * C_B + (f - C_A));
        unsigned long long v;
        asm("mov.b64 %0, {%1, %2};" : "=l"(v) : "f"(lo), "f"(hi));
        g_Wp[t] = v;
    }
}

// ---------------------------------------------------------------------------
// Main fused kernel: one warp owns G=4 output points.
// Phase 1: accumulate Sa[k][c], Sb[k][c], imp_sum (warp-private, no atomics)
// Phase 2: einsum over 288 terms via packed FFMA2: s-pairs come free from
//          LDS.128 (contiguous t), w-pairs from the pair-major LDG.64 table,
//          reused across all G outputs.
// No __syncthreads anywhere: every shared word is touched by exactly one warp.
// ---------------------------------------------------------------------------
__global__ __launch_bounds__(WARPS_PER_BLK * 32, 6)
void sparse_conv_kernel(const float* __restrict__ feats,
                        const float* __restrict__ ba,
                        const float* __restrict__ bb,
                        float* __restrict__ out) {
    __shared__ __align__(16) float sm[SMEM_FLOATS];

    const int lane = threadIdx.x & 31;
    const int warp = threadIdx.x >> 5;
    float* Sw = sm + warp * (G * PER_OUT);
    const int o0 = (blockIdx.x * WARPS_PER_BLK + warp) * G;

    // Coalesced prefetch of this warp's G+1 row bounds (lane i holds bound i).
    int myBound = 0;
    if (lane <= G) myBound = g_row_start[o0 + lane];

    // Zero this warp's private region.
    #pragma unroll
    for (int g = 0; g < G; ++g) {
        float* p = Sw + g * PER_OUT;
        #pragma unroll
        for (int i = 0; i < KK; ++i) {
            p[i * 32 + lane]          = 0.f;
            p[SB_OFF + i * 32 + lane] = 0.f;
        }
    }

    float imps[G];

    // ---------------- Phase 1: edge accumulation ----------------
    for (int g = 0; g < G; ++g) {
        float* sa = Sw + g * PER_OUT;
        float* sb = sa + SB_OFF;
        const int e0 = __shfl_sync(0xffffffffu, myBound, g);
        const int e1 = __shfl_sync(0xffffffffu, myBound, g + 1);

        float ip = 0.f;
        #pragma unroll 1
        for (int base = e0; base < e1; base += 32) {
            const int n = min(32, e1 - base);
            unsigned pk = 0u;
            float    im = 0.f;
            if (lane < n) {
                pk = g_packed[base + lane];
                im = g_impe[base + lane];
            }
            ip += im;

            int j = 0;
            // 4 independent feats-row gathers in flight per step
            #pragma unroll 1
            for (; j + 4 <= n; j += 4) {
                const unsigned p0 = __shfl_sync(0xffffffffu, pk, j);
                const unsigned p1 = __shfl_sync(0xffffffffu, pk, j + 1);
                const unsigned p2 = __shfl_sync(0xffffffffu, pk, j + 2);
                const unsigned p3 = __shfl_sync(0xffffffffu, pk, j + 3);
                const float v0 = __ldg(feats + (p0 & 0xFFFFFFu) * C_IN + lane);
                const float v1 = __ldg(feats + (p1 & 0xFFFFFFu) * C_IN + lane);
                const float v2 = __ldg(feats + (p2 & 0xFFFFFFu) * C_IN + lane);
                const float v3 = __ldg(feats + (p3 & 0xFFFFFFu) * C_IN + lane);
                const float m0 = __shfl_sync(0xffffffffu, im, j);
                const float m1 = __shfl_sync(0xffffffffu, im, j + 1);
                const float m2 = __shfl_sync(0xffffffffu, im, j + 2);
                const float m3 = __shfl_sync(0xffffffffu, im, j + 3);
                const int k0 = (int)(p0 >> 24), k1 = (int)(p1 >> 24);
                const int k2 = (int)(p2 >> 24), k3 = (int)(p3 >> 24);
                sa[k0 * 32 + lane] += v0;  sb[k0 * 32 + lane] += v0 * m0;
                sa[k1 * 32 + lane] += v1;  sb[k1 * 32 + lane] += v1 * m1;
                sa[k2 * 32 + lane] += v2;  sb[k2 * 32 + lane] += v2 * m2;
                sa[k3 * 32 + lane] += v3;  sb[k3 * 32 + lane] += v3 * m3;
            }
            #pragma unroll 1
            for (; j < n; ++j) {
                const unsigned pj = __shfl_sync(0xffffffffu, pk, j);
                const float    mj = __shfl_sync(0xffffffffu, im, j);
                const float    v  = __ldg(feats + (pj & 0xFFFFFFu) * C_IN + lane);
                const int      kj = (int)(pj >> 24);
                sa[kj * 32 + lane] += v;
                sb[kj * 32 + lane] += v * mj;
            }
        }

        #pragma unroll
        for (int s = 16; s > 0; s >>= 1)
            ip += __shfl_xor_sync(0xffffffffu, ip, s);
        imps[g] = ip;
    }

    // ---------------- Phase 2: packed-f32x2 einsum ----------------
    // lane f<24 -> branch A (Sa, W_a); lanes 24..31 -> branch B (Sb, W_b).
    const int selOff = (lane < C_A) ? 0 : SB_OFF;

    unsigned long long acc2[G];
    #pragma unroll
    for (int g = 0; g < G; ++g) acc2[g] = 0ull;  // (0.0f, 0.0f)

    #pragma unroll 1
    for (int p0 = 0; p0 < P_TOT; p0 += 4) {      // 36 iterations, 8 t-values each
        const unsigned long long w0 = g_Wp[(p0 + 0) * 32 + lane];
        const unsigned long long w1 = g_Wp[(p0 + 1) * 32 + lane];
        const unsigned long long w2 = g_Wp[(p0 + 2) * 32 + lane];
        const unsigned long long w3 = g_Wp[(p0 + 3) * 32 + lane];
        #pragma unroll
        for (int g = 0; g < G; ++g) {
            const float* sp = Sw + g * PER_OUT + selOff + 2 * p0;
            const ulonglong2 s01 = *reinterpret_cast<const ulonglong2*>(sp);
            const ulonglong2 s23 = *reinterpret_cast<const ulonglong2*>(sp + 4);
            FFMA2(acc2[g], s01.x, w0);
            FFMA2(acc2[g], s01.y, w1);
            FFMA2(acc2[g], s23.x, w2);
            FFMA2(acc2[g], s23.y, w3);
        }
    }

    const float bias = (lane < C_A) ? __ldg(ba + lane) : __ldg(bb + lane - C_A);
    #pragma unroll
    for (int g = 0; g < G; ++g) {
        float alo, ahi;
        asm("mov.b64 {%0, %1}, %2;" : "=f"(alo), "=f"(ahi) : "l"(acc2[g]));
        const float acc = alo + ahi;
        const int o = o0 + g;
        const float isum  = imps[g];
        const float denom = (isum > 0.f) ? isum : 1.f;
        float r = (lane < C_A) ? (acc + bias) : (acc / denom + bias);
        out[o * 32 + lane] = fmaxf(r, 0.f);
        if (lane == 0) out[N_OUT * 32 + o] = isum;
    }
}

// ---------------------------------------------------------------------------
extern "C" void kernel_launch(void* const* d_in, const int* in_sizes, int n_in,
                              void* d_out, int out_size) {
    const float* feats      = (const float*)d_in[0];
    const float* importance = (const float*)d_in[1];
    const float* W_a        = (const float*)d_in[2];
    const float* b_a        = (const float*)d_in[3];
    const float* W_b        = (const float*)d_in[4];
    const float* b_b        = (const float*)d_in[5];
    const int*   n_idx      = (const int*)d_in[6];
    const int*   n_kidx     = (const int*)d_in[7];
    const int*   n_oidx     = (const int*)d_in[8];
    float* out = (float*)d_out;

    const int e_count = in_sizes[6];
    const int prep_threads = (e_count > N_OUT + 1) ? e_count : (N_OUT + 1);

    prepass_kernel<<<(prep_threads + 255) / 256, 256>>>(
        n_idx, n_kidx, importance, n_oidx, W_a, W_b, e_count);
    sparse_conv_kernel<<<N_OUT / OUT_PER_BLK, WARPS_PER_BLK * 32>>>(
        feats, b_a, b_b, out);
}